// round 15
// baseline (speedup 1.0000x reference)
#include <cuda_runtime.h>
#include <cuda_fp16.h>
#include <math.h>
#include <stdint.h>

// Problem shapes (fixed by the dataset)
#define T_MAX 262144
#define B_MAX 4096
#define F_DIM 128
#define H_DIM 256
#define C_DIM 512
#define KV_DIM 512

// ---------------------------------------------------------------------------
// Scratch (allocation-free rule: __device__ globals)
// ---------------------------------------------------------------------------
__device__ __half g_objh[(size_t)T_MAX * F_DIM];      // 64 MB
__device__ __half g_ctxh[(size_t)B_MAX * C_DIM];      // 4 MB
__device__ __half g_h1 [(size_t)T_MAX * H_DIM];       // 128 MB
__device__ __half g_h2 [(size_t)T_MAX * H_DIM];       // 128 MB
__device__ float  g_rr [(size_t)B_MAX * H_DIM];       // 4 MB  rr = q @ W3k^T (fused)
__device__ float  g_lp [(size_t)T_MAX];               // 1 MB  logit partial (unscaled)
__device__ __half g_hbarh[(size_t)B_MAX * H_DIM];     // 2 MB  hbar = sum w*h2
__device__ __half g_Wt1[H_DIM * F_DIM];               // W1^T [N][K] fp16
__device__ __half g_Wt2[H_DIM * H_DIM];               // W2^T
__device__ __half g_Wt3v[H_DIM * H_DIM];              // W3v^T [n][h] = W3[h, 256+n]
__device__ __half g_Wtrr[H_DIM * C_DIM];              // fused (Wq @ W3k^T)^T [h][c]
__device__ float  g_brr[H_DIM];                       // bq @ W3k^T
__device__ float  g_u[C_DIM];                         // Wq @ b3k
__device__ float  g_c0[1];                            // bq . b3k
__device__ int    g_segstart[B_MAX + 1];

// ---------------------------------------------------------------------------
// Helpers
// ---------------------------------------------------------------------------
__device__ __forceinline__ uint32_t smem_u32(const void* p) {
    uint32_t a;
    asm("{ .reg .u64 t; cvta.to.shared.u64 t, %1; cvt.u32.u64 %0, t; }" : "=r"(a) : "l"(p));
    return a;
}

#define CP_ASYNC16(dst, src) \
    asm volatile("cp.async.cg.shared.global [%0], [%1], 16;" :: "r"(dst), "l"(src) : "memory")
#define CP_COMMIT() asm volatile("cp.async.commit_group;" ::: "memory")
#define CP_WAIT0()  asm volatile("cp.async.wait_group 0;" ::: "memory")
#define CP_WAIT1()  asm volatile("cp.async.wait_group 1;" ::: "memory")

#define LDSM_X4(r0, r1, r2, r3, addr) \
    asm volatile("ldmatrix.sync.aligned.m8n8.x4.shared.b16 {%0,%1,%2,%3}, [%4];" \
        : "=r"(r0), "=r"(r1), "=r"(r2), "=r"(r3) : "r"(addr))

// mma.sync m16n8k16 fp16 -> fp32 accumulate
__device__ __forceinline__ void mma_fp16(float* c, const uint32_t* a, const uint32_t* b) {
    asm volatile(
        "mma.sync.aligned.m16n8k16.row.col.f32.f16.f16.f32 "
        "{%0,%1,%2,%3}, {%4,%5,%6,%7}, {%8,%9}, {%0,%1,%2,%3};"
        : "+f"(c[0]), "+f"(c[1]), "+f"(c[2]), "+f"(c[3])
        : "r"(a[0]), "r"(a[1]), "r"(a[2]), "r"(a[3]), "r"(b[0]), "r"(b[1]));
}

// Stage layout: BK=64 halves (128 B data/row), row stride 144 B (bank-free).
#define ROW_B 144
#define STAGE_BYTES (2 * 128 * ROW_B)        // 36864 B
#define NSTAGE 3
#define GEMM_SMEM (NSTAGE * STAGE_BYTES)     // 110592 B -> 2 CTA/SM

// ---------------------------------------------------------------------------
// Mainloop (round-9 best): 128x128 tile, BK=64, 3-stage cp.async, ldmatrix.
// ---------------------------------------------------------------------------
__device__ __forceinline__ void gemm_mainloop(
    uint32_t sb,
    const __half* __restrict__ Ablk, const __half* __restrict__ Bblk,
    int K, int tid, float acc[2][8][4])
{
    const int wid = tid >> 5, lane = tid & 31;
    const int wm = wid >> 1, wn = wid & 1;
    const int lm_r = lane & 15;
    const int lm_k = (lane >> 4) * 16;

    auto load_stage = [&](int s, int kblk) {
        const __half* Asrc = Ablk + kblk * 64;
        const __half* Bsrc = Bblk + kblk * 64;
        uint32_t abase = sb + (uint32_t)s * STAGE_BYTES;
        uint32_t bbase = abase + 128 * ROW_B;
#pragma unroll
        for (int i = 0; i < 4; i++) {
            int idx = tid + i * 256;
            int row = idx >> 3, k16 = idx & 7;
            CP_ASYNC16(abase + (uint32_t)(row * ROW_B + k16 * 16), Asrc + (size_t)row * K + k16 * 8);
            CP_ASYNC16(bbase + (uint32_t)(row * ROW_B + k16 * 16), Bsrc + (size_t)row * K + k16 * 8);
        }
        CP_COMMIT();
    };

#pragma unroll
    for (int mf = 0; mf < 2; mf++)
#pragma unroll
        for (int nf = 0; nf < 8; nf++)
#pragma unroll
            for (int j = 0; j < 4; j++) acc[mf][nf][j] = 0.f;

    const int nk = K >> 6;
    load_stage(0, 0);
    if (nk > 1) load_stage(1, 1);

    for (int c = 0; c < nk; c++) {
        if (c + 1 < nk) CP_WAIT1(); else CP_WAIT0();
        __syncthreads();
        if (c + 2 < nk) load_stage((c + 2) % NSTAGE, c + 2);

        const uint32_t Ab = sb + (uint32_t)(c % NSTAGE) * STAGE_BYTES;
        const uint32_t Bb = Ab + 128 * ROW_B;

#pragma unroll
        for (int ks = 0; ks < 4; ks++) {
            uint32_t a[2][4], b[8][2];
#pragma unroll
            for (int mf = 0; mf < 2; mf++) {
                uint32_t addr = Ab + (uint32_t)((wm * 32 + mf * 16 + lm_r) * ROW_B + ks * 32) + lm_k;
                LDSM_X4(a[mf][0], a[mf][1], a[mf][2], a[mf][3], addr);
            }
#pragma unroll
            for (int p = 0; p < 4; p++) {
                uint32_t addr = Bb + (uint32_t)((wn * 64 + p * 16 + lm_r) * ROW_B + ks * 32) + lm_k;
                LDSM_X4(b[2 * p][0], b[2 * p + 1][0], b[2 * p][1], b[2 * p + 1][1], addr);
            }
#pragma unroll
            for (int mf = 0; mf < 2; mf++)
#pragma unroll
                for (int nf = 0; nf < 8; nf++)
                    mma_fp16(acc[mf][nf], a[mf], b[nf]);
        }
    }
    __syncthreads();
}

// ---------------------------------------------------------------------------
// Standard GEMM: MODE 0 = fp32 out, MODE 1 = fp16 out (+optional relu)
// ---------------------------------------------------------------------------
template <bool RELU, int MODE>
__global__ __launch_bounds__(256, 2) void gemm_std(
    const __half* __restrict__ A, const __half* __restrict__ Wt,
    const float* __restrict__ bias,
    float* __restrict__ Cf, __half* __restrict__ Ch,
    int M, int N, int K)
{
    extern __shared__ uint32_t dyn[];
    const uint32_t sb = smem_u32(dyn);
    const int tid = threadIdx.x;
    const int wid = tid >> 5, lane = tid & 31;
    const int g = lane >> 2, tg = lane & 3;
    const int wm = wid >> 1, wn = wid & 1;

    const size_t m0 = (size_t)blockIdx.y * 128;
    const size_t n0 = (size_t)blockIdx.x * 128;

    float acc[2][8][4];
    gemm_mainloop(sb, A + m0 * K, Wt + n0 * K, K, tid, acc);

#pragma unroll
    for (int mf = 0; mf < 2; mf++) {
        size_t row0 = m0 + wm * 32 + mf * 16 + g;
#pragma unroll
        for (int nf = 0; nf < 8; nf++) {
            int col = (int)n0 + wn * 64 + nf * 8 + tg * 2;
            float b0 = bias[col], b1 = bias[col + 1];
            float v0 = acc[mf][nf][0] + b0;
            float v1 = acc[mf][nf][1] + b1;
            float v2 = acc[mf][nf][2] + b0;
            float v3 = acc[mf][nf][3] + b1;
            if (RELU) { v0 = fmaxf(v0, 0.f); v1 = fmaxf(v1, 0.f); v2 = fmaxf(v2, 0.f); v3 = fmaxf(v3, 0.f); }
            if (MODE == 0) {
                *reinterpret_cast<float2*>(Cf + row0 * N + col)       = make_float2(v0, v1);
                *reinterpret_cast<float2*>(Cf + (row0 + 8) * N + col) = make_float2(v2, v3);
            } else {
                *reinterpret_cast<__half2*>(Ch + row0 * N + col)       = __floats2half2_rn(v0, v1);
                *reinterpret_cast<__half2*>(Ch + (row0 + 8) * N + col) = __floats2half2_rn(v2, v3);
            }
        }
    }
}

// ---------------------------------------------------------------------------
// Logits: lp[t] = rr[seg[t]] . h2[t]   (unscaled; /16 and +e in segreduce)
// Warp per row: lane reads 8 halves of h2 (uint4) and 8 floats of rr.
// ---------------------------------------------------------------------------
__global__ __launch_bounds__(256) void logits_kernel(
    const int* __restrict__ seg, const float* __restrict__ rr,
    float* __restrict__ lp, int T)
{
    const int t = blockIdx.x * 8 + (threadIdx.x >> 5);
    if (t >= T) return;
    const int lane = threadIdx.x & 31;

    const __half* h2row = g_h2 + (size_t)t * H_DIM + lane * 8;
    const float*  rrow  = rr + (size_t)__ldg(seg + t) * H_DIM + lane * 8;

    uint4 hv = *reinterpret_cast<const uint4*>(h2row);
    float4 r0 = *reinterpret_cast<const float4*>(rrow);
    float4 r1 = *reinterpret_cast<const float4*>(rrow + 4);

    __half2 h0 = *reinterpret_cast<__half2*>(&hv.x);
    __half2 h1 = *reinterpret_cast<__half2*>(&hv.y);
    __half2 h2v = *reinterpret_cast<__half2*>(&hv.z);
    __half2 h3 = *reinterpret_cast<__half2*>(&hv.w);

    float2 f0 = __half22float2(h0), f1 = __half22float2(h1);
    float2 f2 = __half22float2(h2v), f3 = __half22float2(h3);

    float s = f0.x * r0.x + f0.y * r0.y + f1.x * r0.z + f1.y * r0.w
            + f2.x * r1.x + f2.y * r1.y + f3.x * r1.z + f3.y * r1.w;
#pragma unroll
    for (int o = 16; o; o >>= 1) s += __shfl_xor_sync(0xffffffffu, s, o);
    if (lane == 0) lp[t] = s;
}

// ---------------------------------------------------------------------------
// Weight fusion (fp32): Wtrr[h][c] = sum_n Wq[c,n]*W3[h,n]   (h<256, c<512)
//                       brr[h] = bq @ W3k^T[h];  u[c] = Wq[c,:] . b3k;  c0 = bq.b3k
// grid 257 blocks x 256 threads (block 256 computes u/c0)
// ---------------------------------------------------------------------------
__global__ void wfuse_kernel(
    const float* __restrict__ Wq, const float* __restrict__ W3,
    const float* __restrict__ bq, const float* __restrict__ b3)
{
    __shared__ float row[256];
    __shared__ float red[8];
    const int tid = threadIdx.x;
    const int h = blockIdx.x;

    if (h < 256) {
        row[tid] = W3[(size_t)h * KV_DIM + tid];     // W3[h, n], n<256 (k half)
        __syncthreads();
#pragma unroll
        for (int cc = 0; cc < 2; cc++) {
            int c = tid + cc * 256;
            const float* wq = Wq + (size_t)c * H_DIM;
            float s = 0.f;
#pragma unroll 8
            for (int n = 0; n < 256; n++) s = fmaf(wq[n], row[n], s);
            g_Wtrr[(size_t)h * C_DIM + c] = __float2half_rn(s);
        }
        float p = bq[tid] * row[tid];
#pragma unroll
        for (int o = 16; o; o >>= 1) p += __shfl_xor_sync(0xffffffffu, p, o);
        if ((tid & 31) == 0) red[tid >> 5] = p;
        __syncthreads();
        if (tid == 0) {
            float s = 0.f;
#pragma unroll
            for (int i = 0; i < 8; i++) s += red[i];
            g_brr[h] = s;
        }
    } else {
        row[tid] = b3[tid];                          // b3k
        __syncthreads();
#pragma unroll
        for (int cc = 0; cc < 2; cc++) {
            int c = tid + cc * 256;
            const float* wq = Wq + (size_t)c * H_DIM;
            float s = 0.f;
#pragma unroll 8
            for (int n = 0; n < 256; n++) s = fmaf(wq[n], row[n], s);
            g_u[c] = s;
        }
        float p = bq[tid] * row[tid];
#pragma unroll
        for (int o = 16; o; o >>= 1) p += __shfl_xor_sync(0xffffffffu, p, o);
        if ((tid & 31) == 0) red[tid >> 5] = p;
        __syncthreads();
        if (tid == 0) {
            float s = 0.f;
#pragma unroll
            for (int i = 0; i < 8; i++) s += red[i];
            g_c0[0] = s;
        }
    }
}

// ---------------------------------------------------------------------------
// Merged prep: obj cvt | ctx cvt | W1t | W2t | W3v t | segstart
// ---------------------------------------------------------------------------
#define OBJ_BLK   (T_MAX * F_DIM / 4 / 256)            // 32768
#define CTX_BLK   (B_MAX * C_DIM / 4 / 256)            // 512
#define W1_BLK    (F_DIM * H_DIM / 256)                // 128
#define W2_BLK    (H_DIM * H_DIM / 256)                // 256
#define W3V_BLK   (H_DIM * H_DIM / 256)                // 256
#define SEG_BLK   (T_MAX / 256)                        // 1024
#define PREP_BLOCKS (OBJ_BLK + CTX_BLK + W1_BLK + W2_BLK + W3V_BLK + SEG_BLK)

__device__ __forceinline__ void cvt_range(const float* in, __half* out, int i) {
    float4 v = reinterpret_cast<const float4*>(in)[i];
    reinterpret_cast<__half2*>(out)[i * 2]     = __floats2half2_rn(v.x, v.y);
    reinterpret_cast<__half2*>(out)[i * 2 + 1] = __floats2half2_rn(v.z, v.w);
}
__device__ __forceinline__ void tr_range(const float* W, __half* Wt, int K, int N, int i) {
    int k = i / N, n = i - k * N;
    Wt[(size_t)n * K + k] = __float2half_rn(W[i]);
}

__global__ void prep_all(
    const float* __restrict__ objects, const float* __restrict__ context,
    const float* __restrict__ W1, const float* __restrict__ W2,
    const float* __restrict__ W3, const int* __restrict__ seg, int T, int B)
{
    int b = blockIdx.x;
    int t = threadIdx.x;
    if (b < OBJ_BLK) { cvt_range(objects, g_objh, b * 256 + t); return; }
    b -= OBJ_BLK;
    if (b < CTX_BLK) { cvt_range(context, g_ctxh, b * 256 + t); return; }
    b -= CTX_BLK;
    if (b < W1_BLK) { tr_range(W1, g_Wt1, F_DIM, H_DIM, b * 256 + t); return; }
    b -= W1_BLK;
    if (b < W2_BLK) { tr_range(W2, g_Wt2, H_DIM, H_DIM, b * 256 + t); return; }
    b -= W2_BLK;
    if (b < W3V_BLK) {
        int i = b * 256 + t;
        int h = i >> 8, n = i & 255;
        g_Wt3v[(size_t)n * H_DIM + h] = __float2half_rn(W3[(size_t)h * KV_DIM + 256 + n]);
        return;
    }
    b -= W3V_BLK;
    {   // segstart
        int i = b * 256 + t;
        if (i == 0) { g_segstart[seg[0]] = 0; g_segstart[B] = T; }
        if (i > 0 && i < T) {
            int s = seg[i];
            if (s != seg[i - 1]) g_segstart[s] = i;
        }
    }
}

// ---------------------------------------------------------------------------
// Per-segment: e = ctx.u + c0; softmax over (lp+e)/16; write w; hbar=sum w*h2.
// One 256-thread block per segment.
// ---------------------------------------------------------------------------
__global__ __launch_bounds__(256) void segreduce_kernel(
    const float* __restrict__ lp, const float* __restrict__ ctx,
    float* __restrict__ wout)
{
    const int s = blockIdx.x;
    const int s0 = g_segstart[s];
    const int s1 = g_segstart[s + 1];
    const int tid = threadIdx.x;

    __shared__ float red[8];
    __shared__ float bcast;

    // e_s = ctx_s . u + c0
    {
        const float* c = ctx + (size_t)s * C_DIM;
        float p = c[tid] * g_u[tid] + c[tid + 256] * g_u[tid + 256];
#pragma unroll
        for (int o = 16; o; o >>= 1) p += __shfl_xor_sync(0xffffffffu, p, o);
        if ((tid & 31) == 0) red[tid >> 5] = p;
        __syncthreads();
        if (tid == 0) {
            float e = g_c0[0];
#pragma unroll
            for (int i = 0; i < 8; i++) e += red[i];
            bcast = e;
        }
        __syncthreads();
    }
    const float e = bcast;
    __syncthreads();

    float m = -INFINITY;
    for (int t = s0 + tid; t < s1; t += 256)
        m = fmaxf(m, (lp[t] + e) * 0.0625f);
#pragma unroll
    for (int o = 16; o; o >>= 1) m = fmaxf(m, __shfl_xor_sync(0xffffffffu, m, o));
    if ((tid & 31) == 0) red[tid >> 5] = m;
    __syncthreads();
    if (tid == 0) {
        float mm = red[0];
#pragma unroll
        for (int i = 1; i < 8; i++) mm = fmaxf(mm, red[i]);
        bcast = mm;
    }
    __syncthreads();
    m = bcast;
    __syncthreads();

    float z = 0.f;
    for (int t = s0 + tid; t < s1; t += 256)
        z += __expf((lp[t] + e) * 0.0625f - m);
#pragma unroll
    for (int o = 16; o; o >>= 1) z += __shfl_xor_sync(0xffffffffu, z, o);
    if ((tid & 31) == 0) red[tid >> 5] = z;
    __syncthreads();
    if (tid == 0) {
        float zz = 0.f;
#pragma unroll
        for (int i = 0; i < 8; i++) zz += red[i];
        bcast = zz;
    }
    __syncthreads();
    const float inv = 1.f / bcast;
    __syncthreads();

    for (int t = s0 + tid; t < s1; t += 256)
        wout[t] = __expf((lp[t] + e) * 0.0625f - m) * inv;
    __syncthreads();

    // hbar_s[col=tid] = sum_t w_t * h2[t, tid]
    float acc = 0.f;
    for (int t = s0; t < s1; t++) {
        float w = wout[t];
        acc = fmaf(w, __half2float(g_h2[(size_t)t * H_DIM + tid]), acc);
    }
    g_hbarh[(size_t)s * H_DIM + tid] = __float2half_rn(acc);
}

// ---------------------------------------------------------------------------
// Launch
// ---------------------------------------------------------------------------
extern "C" void kernel_launch(void* const* d_in, const int* in_sizes, int n_in,
                              void* d_out, int out_size)
{
    const float* objects = (const float*)d_in[0];
    const float* context = (const float*)d_in[1];
    const int*   seg     = (const int*)  d_in[2];
    const float* W1 = (const float*)d_in[3];
    const float* b1 = (const float*)d_in[4];
    const float* W2 = (const float*)d_in[5];
    const float* b2 = (const float*)d_in[6];
    const float* W3 = (const float*)d_in[7];
    const float* b3 = (const float*)d_in[8];
    const float* Wq = (const float*)d_in[9];
    const float* bq = (const float*)d_in[10];

    const int T = in_sizes[2];                 // 262144
    const int B = in_sizes[1] / C_DIM;         // 4096

    float* out = (float*)d_out;
    float* emb_out = out;
    float* w_out   = out + (size_t)B * H_DIM;

    __half *p_objh, *p_ctxh, *p_h1, *p_h2, *p_hbarh, *p_w1, *p_w2, *p_w3v, *p_wrr;
    float *p_rr, *p_lp, *p_brr;
    cudaGetSymbolAddress((void**)&p_objh, g_objh);
    cudaGetSymbolAddress((void**)&p_ctxh, g_ctxh);
    cudaGetSymbolAddress((void**)&p_h1, g_h1);
    cudaGetSymbolAddress((void**)&p_h2, g_h2);
    cudaGetSymbolAddress((void**)&p_hbarh, g_hbarh);
    cudaGetSymbolAddress((void**)&p_rr, g_rr);
    cudaGetSymbolAddress((void**)&p_lp, g_lp);
    cudaGetSymbolAddress((void**)&p_w1, g_Wt1);
    cudaGetSymbolAddress((void**)&p_w2, g_Wt2);
    cudaGetSymbolAddress((void**)&p_w3v, g_Wt3v);
    cudaGetSymbolAddress((void**)&p_wrr, g_Wtrr);
    cudaGetSymbolAddress((void**)&p_brr, g_brr);

    cudaFuncSetAttribute(gemm_std<false, 0>, cudaFuncAttributeMaxDynamicSharedMemorySize, GEMM_SMEM);
    cudaFuncSetAttribute(gemm_std<true, 1>,  cudaFuncAttributeMaxDynamicSharedMemorySize, GEMM_SMEM);

    // Weight fusion (fp32) + merged prep
    wfuse_kernel<<<257, 256>>>(Wq, W3, bq, b3);
    prep_all<<<PREP_BLOCKS, 256>>>(objects, context, W1, W2, W3, seg, T, B);

    // rr = ctx @ Wtrr^T + brr   [4096,512] -> [4096,256] fp32 (replaces q GEMM)
    gemm_std<false, 0><<<dim3(H_DIM / 128, B / 128), 256, GEMM_SMEM>>>(
        p_ctxh, p_wrr, p_brr, p_rr, nullptr, B, H_DIM, C_DIM);
    // h1 = relu(objects @ W1 + b1)  fp16 out
    gemm_std<true, 1><<<dim3(H_DIM / 128, T / 128), 256, GEMM_SMEM>>>(
        p_objh, p_w1, b1, nullptr, p_h1, T, H_DIM, F_DIM);
    // h2 = relu(h1 @ W2 + b2)  fp16 out
    gemm_std<true, 1><<<dim3(H_DIM / 128, T / 128), 256, GEMM_SMEM>>>(
        p_h1, p_w2, b2, nullptr, p_h2, T, H_DIM, H_DIM);

    // logits: lp[t] = rr[seg[t]] . h2[t]  (streaming, no GEMM)
    logits_kernel<<<T / 8, 256>>>(seg, p_rr, p_lp, T);

    // softmax + w + hbar = sum w*h2
    segreduce_kernel<<<B, 256>>>(p_lp, context, w_out);

    // emb = hbar @ W3v^T + b3v   [4096,256] -> [4096,256] fp32
    gemm_std<false, 0><<<dim3(H_DIM / 128, B / 128), 256, GEMM_SMEM>>>(
        p_hbarh, p_w3v, b3 + H_DIM, emb_out, nullptr, B, H_DIM, H_DIM);
}

// round 16
// speedup vs baseline: 1.2765x; 1.2765x over previous
#include <cuda_runtime.h>
#include <cuda_fp16.h>
#include <math.h>
#include <stdint.h>

// Problem shapes (fixed by the dataset)
#define T_MAX 262144
#define B_MAX 4096
#define F_DIM 128
#define H_DIM 256
#define C_DIM 512
#define KV_DIM 512

// ---------------------------------------------------------------------------
// Scratch (allocation-free rule: __device__ globals)
// ---------------------------------------------------------------------------
__device__ __half g_objh[(size_t)T_MAX * F_DIM];      // 64 MB
__device__ __half g_ctxh[(size_t)B_MAX * C_DIM];      // 4 MB
__device__ __half g_h1 [(size_t)T_MAX * H_DIM];       // 128 MB
__device__ __half g_h2 [(size_t)T_MAX * H_DIM];       // 128 MB
__device__ float  g_rr [(size_t)B_MAX * H_DIM];       // 4 MB  rr = q @ W3k^T (fused)
__device__ float  g_lp [2 * (size_t)T_MAX];           // 2 MB  logit partials (unscaled)
__device__ __half g_hbarh[(size_t)B_MAX * H_DIM];     // 2 MB  hbar = sum w*h2
__device__ float  g_WqT[(size_t)H_DIM * C_DIM];       // 512 KB Wq^T [n][c] fp32
__device__ __half g_Wt1[H_DIM * F_DIM];               // W1^T [N][K] fp16
__device__ __half g_Wt2[H_DIM * H_DIM];               // W2^T
__device__ __half g_Wt3v[H_DIM * H_DIM];              // W3v^T [n][h] = W3[h, 256+n]
__device__ __half g_Wtrr[H_DIM * C_DIM];              // fused (Wq @ W3k^T)^T [h][c]
__device__ float  g_brr[H_DIM];                       // bq @ W3k^T
__device__ float  g_u[C_DIM];                         // Wq @ b3k
__device__ float  g_c0[1];                            // bq . b3k
__device__ int    g_segstart[B_MAX + 1];

// ---------------------------------------------------------------------------
// Helpers
// ---------------------------------------------------------------------------
__device__ __forceinline__ uint32_t smem_u32(const void* p) {
    uint32_t a;
    asm("{ .reg .u64 t; cvta.to.shared.u64 t, %1; cvt.u32.u64 %0, t; }" : "=r"(a) : "l"(p));
    return a;
}

#define CP_ASYNC16(dst, src) \
    asm volatile("cp.async.cg.shared.global [%0], [%1], 16;" :: "r"(dst), "l"(src) : "memory")
#define CP_COMMIT() asm volatile("cp.async.commit_group;" ::: "memory")
#define CP_WAIT0()  asm volatile("cp.async.wait_group 0;" ::: "memory")
#define CP_WAIT1()  asm volatile("cp.async.wait_group 1;" ::: "memory")

#define LDSM_X4(r0, r1, r2, r3, addr) \
    asm volatile("ldmatrix.sync.aligned.m8n8.x4.shared.b16 {%0,%1,%2,%3}, [%4];" \
        : "=r"(r0), "=r"(r1), "=r"(r2), "=r"(r3) : "r"(addr))

// mma.sync m16n8k16 fp16 -> fp32 accumulate
__device__ __forceinline__ void mma_fp16(float* c, const uint32_t* a, const uint32_t* b) {
    asm volatile(
        "mma.sync.aligned.m16n8k16.row.col.f32.f16.f16.f32 "
        "{%0,%1,%2,%3}, {%4,%5,%6,%7}, {%8,%9}, {%0,%1,%2,%3};"
        : "+f"(c[0]), "+f"(c[1]), "+f"(c[2]), "+f"(c[3])
        : "r"(a[0]), "r"(a[1]), "r"(a[2]), "r"(a[3]), "r"(b[0]), "r"(b[1]));
}

// Stage layout: BK=64 halves (128 B data/row), row stride 144 B (bank-free).
#define ROW_B 144
#define STAGE_BYTES (2 * 128 * ROW_B)        // 36864 B
#define NSTAGE 3
#define GEMM_SMEM (NSTAGE * STAGE_BYTES)     // 110592 B -> 2 CTA/SM

// ---------------------------------------------------------------------------
// Mainloop (round-9 best): 128x128 tile, BK=64, 3-stage cp.async, ldmatrix.
// ---------------------------------------------------------------------------
__device__ __forceinline__ void gemm_mainloop(
    uint32_t sb,
    const __half* __restrict__ Ablk, const __half* __restrict__ Bblk,
    int K, int tid, float acc[2][8][4])
{
    const int wid = tid >> 5, lane = tid & 31;
    const int wm = wid >> 1, wn = wid & 1;
    const int lm_r = lane & 15;
    const int lm_k = (lane >> 4) * 16;

    auto load_stage = [&](int s, int kblk) {
        const __half* Asrc = Ablk + kblk * 64;
        const __half* Bsrc = Bblk + kblk * 64;
        uint32_t abase = sb + (uint32_t)s * STAGE_BYTES;
        uint32_t bbase = abase + 128 * ROW_B;
#pragma unroll
        for (int i = 0; i < 4; i++) {
            int idx = tid + i * 256;
            int row = idx >> 3, k16 = idx & 7;
            CP_ASYNC16(abase + (uint32_t)(row * ROW_B + k16 * 16), Asrc + (size_t)row * K + k16 * 8);
            CP_ASYNC16(bbase + (uint32_t)(row * ROW_B + k16 * 16), Bsrc + (size_t)row * K + k16 * 8);
        }
        CP_COMMIT();
    };

#pragma unroll
    for (int mf = 0; mf < 2; mf++)
#pragma unroll
        for (int nf = 0; nf < 8; nf++)
#pragma unroll
            for (int j = 0; j < 4; j++) acc[mf][nf][j] = 0.f;

    const int nk = K >> 6;
    load_stage(0, 0);
    if (nk > 1) load_stage(1, 1);

    for (int c = 0; c < nk; c++) {
        if (c + 1 < nk) CP_WAIT1(); else CP_WAIT0();
        __syncthreads();
        if (c + 2 < nk) load_stage((c + 2) % NSTAGE, c + 2);

        const uint32_t Ab = sb + (uint32_t)(c % NSTAGE) * STAGE_BYTES;
        const uint32_t Bb = Ab + 128 * ROW_B;

#pragma unroll
        for (int ks = 0; ks < 4; ks++) {
            uint32_t a[2][4], b[8][2];
#pragma unroll
            for (int mf = 0; mf < 2; mf++) {
                uint32_t addr = Ab + (uint32_t)((wm * 32 + mf * 16 + lm_r) * ROW_B + ks * 32) + lm_k;
                LDSM_X4(a[mf][0], a[mf][1], a[mf][2], a[mf][3], addr);
            }
#pragma unroll
            for (int p = 0; p < 4; p++) {
                uint32_t addr = Bb + (uint32_t)((wn * 64 + p * 16 + lm_r) * ROW_B + ks * 32) + lm_k;
                LDSM_X4(b[2 * p][0], b[2 * p + 1][0], b[2 * p][1], b[2 * p + 1][1], addr);
            }
#pragma unroll
            for (int mf = 0; mf < 2; mf++)
#pragma unroll
                for (int nf = 0; nf < 8; nf++)
                    mma_fp16(acc[mf][nf], a[mf], b[nf]);
        }
    }
    __syncthreads();
}

// ---------------------------------------------------------------------------
// Standard GEMM: MODE 0 = fp32 out, MODE 1 = fp16 out (+optional relu)
// ---------------------------------------------------------------------------
template <bool RELU, int MODE>
__global__ __launch_bounds__(256, 2) void gemm_std(
    const __half* __restrict__ A, const __half* __restrict__ Wt,
    const float* __restrict__ bias,
    float* __restrict__ Cf, __half* __restrict__ Ch,
    int M, int N, int K)
{
    extern __shared__ uint32_t dyn[];
    const uint32_t sb = smem_u32(dyn);
    const int tid = threadIdx.x;
    const int wid = tid >> 5, lane = tid & 31;
    const int g = lane >> 2, tg = lane & 3;
    const int wm = wid >> 1, wn = wid & 1;

    const size_t m0 = (size_t)blockIdx.y * 128;
    const size_t n0 = (size_t)blockIdx.x * 128;

    float acc[2][8][4];
    gemm_mainloop(sb, A + m0 * K, Wt + n0 * K, K, tid, acc);

#pragma unroll
    for (int mf = 0; mf < 2; mf++) {
        size_t row0 = m0 + wm * 32 + mf * 16 + g;
#pragma unroll
        for (int nf = 0; nf < 8; nf++) {
            int col = (int)n0 + wn * 64 + nf * 8 + tg * 2;
            float b0 = bias[col], b1 = bias[col + 1];
            float v0 = acc[mf][nf][0] + b0;
            float v1 = acc[mf][nf][1] + b1;
            float v2 = acc[mf][nf][2] + b0;
            float v3 = acc[mf][nf][3] + b1;
            if (RELU) { v0 = fmaxf(v0, 0.f); v1 = fmaxf(v1, 0.f); v2 = fmaxf(v2, 0.f); v3 = fmaxf(v3, 0.f); }
            if (MODE == 0) {
                *reinterpret_cast<float2*>(Cf + row0 * N + col)       = make_float2(v0, v1);
                *reinterpret_cast<float2*>(Cf + (row0 + 8) * N + col) = make_float2(v2, v3);
            } else {
                *reinterpret_cast<__half2*>(Ch + row0 * N + col)       = __floats2half2_rn(v0, v1);
                *reinterpret_cast<__half2*>(Ch + (row0 + 8) * N + col) = __floats2half2_rn(v2, v3);
            }
        }
    }
}

// ---------------------------------------------------------------------------
// h2 GEMM with fused logits (r14 gemm_k_logits epilogue pattern):
// grid (2, T/128). h2 = relu(h1 @ W2 + b2) stored fp16; lp partial =
// h2[t, n0:n0+128] . rr[seg[t], n0:n0+128] via SMEM-staged rr gather.
// ---------------------------------------------------------------------------
#define QB_STRIDE 132                        // rr tile [128][132] fp32 = 67584 B <= GEMM_SMEM

__global__ __launch_bounds__(256, 2) void gemm_h2_logits(
    const __half* __restrict__ A, const __half* __restrict__ Wt,
    const float* __restrict__ bias,
    __half* __restrict__ h2out, float* __restrict__ lpart,
    const float* __restrict__ rr, const int* __restrict__ seg, int M)
{
    extern __shared__ uint32_t dyn[];
    __shared__ int   s_seg[128];
    __shared__ float s_logit[128];
    const uint32_t sb = smem_u32(dyn);

    const int tid = threadIdx.x;
    const int wid = tid >> 5, lane = tid & 31;
    const int g = lane >> 2, tg = lane & 3;
    const int wm = wid >> 1, wn = wid & 1;

    const size_t t0 = (size_t)blockIdx.y * 128;
    const int n0 = blockIdx.x * 128;          // 0 or 128

    if (tid < 128) {
        s_seg[tid] = seg[t0 + tid];
        s_logit[tid] = 0.f;
    }

    float acc[2][8][4];
    gemm_mainloop(sb, A + t0 * H_DIM, Wt + (size_t)n0 * H_DIM, H_DIM, tid, acc);

    // Gather rr slice [128 rows][128 cols] into reused smem (coalesced float4)
    float* qb = (float*)dyn;
#pragma unroll
    for (int i = 0; i < 16; i++) {
        int idx = tid + i * 256;
        int row = idx >> 5, c16 = idx & 31;
        float4 v = *reinterpret_cast<const float4*>(
            rr + (size_t)s_seg[row] * H_DIM + n0 + c16 * 4);
        *reinterpret_cast<float4*>(qb + row * QB_STRIDE + c16 * 4) = v;
    }
    __syncthreads();

#pragma unroll
    for (int mf = 0; mf < 2; mf++) {
        int rA = wm * 32 + mf * 16 + g;
        int rB = rA + 8;
        size_t rowA = t0 + rA, rowB = t0 + rB;
        float pA = 0.f, pB = 0.f;
#pragma unroll
        for (int nf = 0; nf < 8; nf++) {
            int cq = wn * 64 + nf * 8 + tg * 2;
            int col = n0 + cq;
            float bb0 = __ldg(bias + col), bb1 = __ldg(bias + col + 1);
            float v0 = fmaxf(acc[mf][nf][0] + bb0, 0.f);
            float v1 = fmaxf(acc[mf][nf][1] + bb1, 0.f);
            float v2 = fmaxf(acc[mf][nf][2] + bb0, 0.f);
            float v3 = fmaxf(acc[mf][nf][3] + bb1, 0.f);
            *reinterpret_cast<__half2*>(h2out + rowA * H_DIM + col) = __floats2half2_rn(v0, v1);
            *reinterpret_cast<__half2*>(h2out + rowB * H_DIM + col) = __floats2half2_rn(v2, v3);
            float q0A = qb[rA * QB_STRIDE + cq], q1A = qb[rA * QB_STRIDE + cq + 1];
            float q0B = qb[rB * QB_STRIDE + cq], q1B = qb[rB * QB_STRIDE + cq + 1];
            pA = fmaf(v0, q0A, pA); pA = fmaf(v1, q1A, pA);
            pB = fmaf(v2, q0B, pB); pB = fmaf(v3, q1B, pB);
        }
        pA += __shfl_xor_sync(0xffffffffu, pA, 1);
        pA += __shfl_xor_sync(0xffffffffu, pA, 2);
        pB += __shfl_xor_sync(0xffffffffu, pB, 1);
        pB += __shfl_xor_sync(0xffffffffu, pB, 2);
        if (tg == 0) {
            atomicAdd(s_logit + rA, pA);
            atomicAdd(s_logit + rB, pB);
        }
    }
    __syncthreads();
    if (tid < 128)
        lpart[(size_t)blockIdx.x * M + t0 + tid] = s_logit[tid];   // unscaled
}

// ---------------------------------------------------------------------------
// Weight fusion (fp32, coalesced via WqT): Wtrr[h][c] = sum_n WqT[n][c]*W3[h,n]
//   brr[h] = bq @ W3k^T[h];  u[c] = sum_n WqT[n][c]*b3k[n];  c0 = bq.b3k
// grid 257 blocks x 256 threads (block 256 computes u/c0)
// ---------------------------------------------------------------------------
__global__ void wfuse_kernel(
    const float* __restrict__ WqT, const float* __restrict__ W3,
    const float* __restrict__ bq, const float* __restrict__ b3)
{
    __shared__ float row[256];
    __shared__ float red[8];
    const int tid = threadIdx.x;
    const int h = blockIdx.x;

    if (h < 256) {
        row[tid] = W3[(size_t)h * KV_DIM + tid];     // W3[h, n], n<256 (k half)
        __syncthreads();
#pragma unroll
        for (int cc = 0; cc < 2; cc++) {
            int c = tid + cc * 256;
            float s = 0.f;
#pragma unroll 8
            for (int n = 0; n < 256; n++) s = fmaf(WqT[(size_t)n * C_DIM + c], row[n], s);
            g_Wtrr[(size_t)h * C_DIM + c] = __float2half_rn(s);
        }
        float p = bq[tid] * row[tid];
#pragma unroll
        for (int o = 16; o; o >>= 1) p += __shfl_xor_sync(0xffffffffu, p, o);
        if ((tid & 31) == 0) red[tid >> 5] = p;
        __syncthreads();
        if (tid == 0) {
            float s = 0.f;
#pragma unroll
            for (int i = 0; i < 8; i++) s += red[i];
            g_brr[h] = s;
        }
    } else {
        row[tid] = b3[tid];                          // b3k
        __syncthreads();
#pragma unroll
        for (int cc = 0; cc < 2; cc++) {
            int c = tid + cc * 256;
            float s = 0.f;
#pragma unroll 8
            for (int n = 0; n < 256; n++) s = fmaf(WqT[(size_t)n * C_DIM + c], row[n], s);
            g_u[c] = s;
        }
        float p = bq[tid] * row[tid];
#pragma unroll
        for (int o = 16; o; o >>= 1) p += __shfl_xor_sync(0xffffffffu, p, o);
        if ((tid & 31) == 0) red[tid >> 5] = p;
        __syncthreads();
        if (tid == 0) {
            float s = 0.f;
#pragma unroll
            for (int i = 0; i < 8; i++) s += red[i];
            g_c0[0] = s;
        }
    }
}

// ---------------------------------------------------------------------------
// Merged prep: obj cvt | ctx cvt | W1t | W2t | W3v t | WqT | segstart
// ---------------------------------------------------------------------------
#define OBJ_BLK   (T_MAX * F_DIM / 4 / 256)            // 32768
#define CTX_BLK   (B_MAX * C_DIM / 4 / 256)            // 512
#define W1_BLK    (F_DIM * H_DIM / 256)                // 128
#define W2_BLK    (H_DIM * H_DIM / 256)                // 256
#define W3V_BLK   (H_DIM * H_DIM / 256)                // 256
#define WQT_BLK   (H_DIM * C_DIM / 256)                // 512
#define SEG_BLK   (T_MAX / 256)                        // 1024
#define PREP_BLOCKS (OBJ_BLK + CTX_BLK + W1_BLK + W2_BLK + W3V_BLK + WQT_BLK + SEG_BLK)

__device__ __forceinline__ void cvt_range(const float* in, __half* out, int i) {
    float4 v = reinterpret_cast<const float4*>(in)[i];
    reinterpret_cast<__half2*>(out)[i * 2]     = __floats2half2_rn(v.x, v.y);
    reinterpret_cast<__half2*>(out)[i * 2 + 1] = __floats2half2_rn(v.z, v.w);
}
__device__ __forceinline__ void tr_range(const float* W, __half* Wt, int K, int N, int i) {
    int k = i / N, n = i - k * N;
    Wt[(size_t)n * K + k] = __float2half_rn(W[i]);
}

__global__ void prep_all(
    const float* __restrict__ objects, const float* __restrict__ context,
    const float* __restrict__ W1, const float* __restrict__ W2,
    const float* __restrict__ W3, const float* __restrict__ Wq,
    const int* __restrict__ seg, int T, int B)
{
    int b = blockIdx.x;
    int t = threadIdx.x;
    if (b < OBJ_BLK) { cvt_range(objects, g_objh, b * 256 + t); return; }
    b -= OBJ_BLK;
    if (b < CTX_BLK) { cvt_range(context, g_ctxh, b * 256 + t); return; }
    b -= CTX_BLK;
    if (b < W1_BLK) { tr_range(W1, g_Wt1, F_DIM, H_DIM, b * 256 + t); return; }
    b -= W1_BLK;
    if (b < W2_BLK) { tr_range(W2, g_Wt2, H_DIM, H_DIM, b * 256 + t); return; }
    b -= W2_BLK;
    if (b < W3V_BLK) {
        int i = b * 256 + t;
        int h = i >> 8, n = i & 255;
        g_Wt3v[(size_t)n * H_DIM + h] = __float2half_rn(W3[(size_t)h * KV_DIM + 256 + n]);
        return;
    }
    b -= W3V_BLK;
    if (b < WQT_BLK) {
        int i = b * 256 + t;                  // 0..131071
        int n = i >> 9, c = i & 511;          // WqT[n][c] = Wq[c][n]
        g_WqT[i] = Wq[(size_t)c * H_DIM + n];
        return;
    }
    b -= WQT_BLK;
    {   // segstart
        int i = b * 256 + t;
        if (i == 0) { g_segstart[seg[0]] = 0; g_segstart[B] = T; }
        if (i > 0 && i < T) {
            int s = seg[i];
            if (s != seg[i - 1]) g_segstart[s] = i;
        }
    }
}

// ---------------------------------------------------------------------------
// Per-segment: e = ctx.u + c0; softmax over (lp0+lp1+e)/16; write w;
// hbar = sum w*h2 (fp16 out). One 256-thread block per segment.
// ---------------------------------------------------------------------------
__global__ __launch_bounds__(256) void segreduce_kernel(
    const float* __restrict__ lp0, const float* __restrict__ lp1,
    const float* __restrict__ ctx, float* __restrict__ wout)
{
    const int s = blockIdx.x;
    const int s0 = g_segstart[s];
    const int s1 = g_segstart[s + 1];
    const int tid = threadIdx.x;

    __shared__ float red[8];
    __shared__ float bcast;

    // e_s = ctx_s . u + c0
    {
        const float* c = ctx + (size_t)s * C_DIM;
        float p = c[tid] * g_u[tid] + c[tid + 256] * g_u[tid + 256];
#pragma unroll
        for (int o = 16; o; o >>= 1) p += __shfl_xor_sync(0xffffffffu, p, o);
        if ((tid & 31) == 0) red[tid >> 5] = p;
        __syncthreads();
        if (tid == 0) {
            float e = g_c0[0];
#pragma unroll
            for (int i = 0; i < 8; i++) e += red[i];
            bcast = e;
        }
        __syncthreads();
    }
    const float e = bcast;
    __syncthreads();

    float m = -INFINITY;
    for (int t = s0 + tid; t < s1; t += 256)
        m = fmaxf(m, (lp0[t] + lp1[t] + e) * 0.0625f);
#pragma unroll
    for (int o = 16; o; o >>= 1) m = fmaxf(m, __shfl_xor_sync(0xffffffffu, m, o));
    if ((tid & 31) == 0) red[tid >> 5] = m;
    __syncthreads();
    if (tid == 0) {
        float mm = red[0];
#pragma unroll
        for (int i = 1; i < 8; i++) mm = fmaxf(mm, red[i]);
        bcast = mm;
    }
    __syncthreads();
    m = bcast;
    __syncthreads();

    float z = 0.f;
    for (int t = s0 + tid; t < s1; t += 256)
        z += __expf((lp0[t] + lp1[t] + e) * 0.0625f - m);
#pragma unroll
    for (int o = 16; o; o >>= 1) z += __shfl_xor_sync(0xffffffffu, z, o);
    if ((tid & 31) == 0) red[tid >> 5] = z;
    __syncthreads();
    if (tid == 0) {
        float zz = 0.f;
#pragma unroll
        for (int i = 0; i < 8; i++) zz += red[i];
        bcast = zz;
    }
    __syncthreads();
    const float inv = 1.f / bcast;
    __syncthreads();

    for (int t = s0 + tid; t < s1; t += 256)
        wout[t] = __expf((lp0[t] + lp1[t] + e) * 0.0625f - m) * inv;
    __syncthreads();

    // hbar_s[col=tid] = sum_t w_t * h2[t, tid]
    float acc = 0.f;
    for (int t = s0; t < s1; t++) {
        float w = wout[t];
        acc = fmaf(w, __half2float(g_h2[(size_t)t * H_DIM + tid]), acc);
    }
    g_hbarh[(size_t)s * H_DIM + tid] = __float2half_rn(acc);
}

// ---------------------------------------------------------------------------
// Launch
// ---------------------------------------------------------------------------
extern "C" void kernel_launch(void* const* d_in, const int* in_sizes, int n_in,
                              void* d_out, int out_size)
{
    const float* objects = (const float*)d_in[0];
    const float* context = (const float*)d_in[1];
    const int*   seg     = (const int*)  d_in[2];
    const float* W1 = (const float*)d_in[3];
    const float* b1 = (const float*)d_in[4];
    const float* W2 = (const float*)d_in[5];
    const float* b2 = (const float*)d_in[6];
    const float* W3 = (const float*)d_in[7];
    const float* b3 = (const float*)d_in[8];
    const float* Wq = (const float*)d_in[9];
    const float* bq = (const float*)d_in[10];

    const int T = in_sizes[2];                 // 262144
    const int B = in_sizes[1] / C_DIM;         // 4096

    float* out = (float*)d_out;
    float* emb_out = out;
    float* w_out   = out + (size_t)B * H_DIM;

    __half *p_objh, *p_ctxh, *p_h1, *p_h2, *p_hbarh, *p_w1, *p_w2, *p_w3v, *p_wrr;
    float *p_rr, *p_lp, *p_brr, *p_wqt;
    cudaGetSymbolAddress((void**)&p_objh, g_objh);
    cudaGetSymbolAddress((void**)&p_ctxh, g_ctxh);
    cudaGetSymbolAddress((void**)&p_h1, g_h1);
    cudaGetSymbolAddress((void**)&p_h2, g_h2);
    cudaGetSymbolAddress((void**)&p_hbarh, g_hbarh);
    cudaGetSymbolAddress((void**)&p_rr, g_rr);
    cudaGetSymbolAddress((void**)&p_lp, g_lp);
    cudaGetSymbolAddress((void**)&p_w1, g_Wt1);
    cudaGetSymbolAddress((void**)&p_w2, g_Wt2);
    cudaGetSymbolAddress((void**)&p_w3v, g_Wt3v);
    cudaGetSymbolAddress((void**)&p_wrr, g_Wtrr);
    cudaGetSymbolAddress((void**)&p_brr, g_brr);
    cudaGetSymbolAddress((void**)&p_wqt, g_WqT);

    cudaFuncSetAttribute(gemm_std<false, 0>, cudaFuncAttributeMaxDynamicSharedMemorySize, GEMM_SMEM);
    cudaFuncSetAttribute(gemm_std<true, 1>,  cudaFuncAttributeMaxDynamicSharedMemorySize, GEMM_SMEM);
    cudaFuncSetAttribute(gemm_h2_logits, cudaFuncAttributeMaxDynamicSharedMemorySize, GEMM_SMEM);

    // Merged prep (builds WqT), then weight fusion (fp32, coalesced)
    prep_all<<<PREP_BLOCKS, 256>>>(objects, context, W1, W2, W3, Wq, seg, T, B);
    wfuse_kernel<<<257, 256>>>(p_wqt, W3, bq, b3);

    // rr = ctx @ Wtrr^T + brr   [4096,512] -> [4096,256] fp32
    gemm_std<false, 0><<<dim3(H_DIM / 128, B / 128), 256, GEMM_SMEM>>>(
        p_ctxh, p_wrr, p_brr, p_rr, nullptr, B, H_DIM, C_DIM);
    // h1 = relu(objects @ W1 + b1)  fp16 out
    gemm_std<true, 1><<<dim3(H_DIM / 128, T / 128), 256, GEMM_SMEM>>>(
        p_objh, p_w1, b1, nullptr, p_h1, T, H_DIM, F_DIM);
    // h2 = relu(h1 @ W2 + b2) fp16 + fused logit partials vs rr[seg]
    gemm_h2_logits<<<dim3(2, T / 128), 256, GEMM_SMEM>>>(
        p_h1, p_w2, b2, p_h2, p_lp, p_rr, seg, T);

    // softmax + w + hbar = sum w*h2
    segreduce_kernel<<<B, 256>>>(p_lp, p_lp + T, context, w_out);

    // emb = hbar @ W3v^T + b3v   [4096,256] -> [4096,256] fp32
    gemm_std<false, 0><<<dim3(H_DIM / 128, B / 128), 256, GEMM_SMEM>>>(
        p_hbarh, p_w3v, b3 + H_DIM, emb_out, nullptr, B, H_DIM, H_DIM);
}